// round 8
// baseline (speedup 1.0000x reference)
#include <cuda_runtime.h>
#include <cstdint>

// Model_55645596287458 — R7: warp-private TMA pipelines (R6b) with
// conflict-free smem access + deeper parallelism.
//  - 148 CTAs x 768 threads; 24 warps/CTA, each owning a 6-slot x 1536B
//    (128-pt) ring.
//  - Lane processes points p = lane + 32*i (i<4): scalar LDS/STS at 12B
//    stride -> word index 3*lane mod 32, gcd(3,32)=1 -> zero bank conflicts.
//  - g2s bulk load (4-deep prefetch), bulk store with wait_group.read 2
//    recycling. No CTA-wide barriers in the hot loop.

#define WARPS     24
#define THREADS   (WARPS * 32)
#define SLOTS     6
#define TILE_PTS  128
#define TILE_B    (TILE_PTS * 12)            // 1536
#define NBLK      148
#define PREF      4
#define SMEM_TILES (WARPS * SLOTS * TILE_B)  // 221184
#define SMEM_DYN   (SMEM_TILES + WARPS * SLOTS * 8)

__device__ float        g_sum   = 0.0f;
__device__ unsigned int g_count = 0u;

__device__ __forceinline__ void mbar_init(uint32_t a, uint32_t cnt) {
    asm volatile("mbarrier.init.shared.b64 [%0], %1;" :: "r"(a), "r"(cnt) : "memory");
}
__device__ __forceinline__ void mbar_expect_tx(uint32_t a, uint32_t bytes) {
    asm volatile("mbarrier.arrive.expect_tx.shared.b64 _, [%0], %1;"
                 :: "r"(a), "r"(bytes) : "memory");
}
__device__ __forceinline__ void mbar_wait_parity(uint32_t a, uint32_t parity) {
    asm volatile(
        "{\n\t.reg .pred P;\n\t"
        "LW_%=:\n\t"
        "mbarrier.try_wait.parity.acquire.cta.shared::cta.b64 P, [%0], %1, 0x989680;\n\t"
        "@P bra.uni LD_%=;\n\t"
        "bra.uni LW_%=;\n\t"
        "LD_%=:\n\t}"
        :: "r"(a), "r"(parity) : "memory");
}
__device__ __forceinline__ void bulk_g2s(uint32_t dst, const void* src,
                                         uint32_t bytes, uint32_t mbar) {
    asm volatile("cp.async.bulk.shared::cta.global.mbarrier::complete_tx::bytes "
                 "[%0], [%1], %2, [%3];"
                 :: "r"(dst), "l"(src), "r"(bytes), "r"(mbar) : "memory");
}
__device__ __forceinline__ void bulk_s2g(void* dst, uint32_t src, uint32_t bytes) {
    asm volatile("cp.async.bulk.global.shared::cta.bulk_group [%0], [%1], %2;"
                 :: "l"(dst), "r"(src), "r"(bytes) : "memory");
}

extern __shared__ char smem_raw[];

__global__ __launch_bounds__(THREADS, 1) void pose_warp_pipe_kernel(
    const float* __restrict__ pts,
    const float* __restrict__ px,  const float* __restrict__ py,
    const float* __restrict__ pz,  const float* __restrict__ proll,
    const float* __restrict__ ppitch, const float* __restrict__ pyaw,
    float* __restrict__ out, int n_pts, int loss_idx)
{
    __shared__ float sRT[12];
    __shared__ float swarp[WARPS];

    const int t    = threadIdx.x;
    const int lane = t & 31;
    const int wid  = t >> 5;
    const int bid  = blockIdx.x;

    const uint32_t smem_base = (uint32_t)__cvta_generic_to_shared(smem_raw);
    const uint32_t mbar_base = smem_base + SMEM_TILES;

    if (t == 0) {
        float roll = *proll, pitch = *ppitch, yaw = *pyaw;
        float cr = cosf(roll),  sr = sinf(roll);
        float cp = cosf(pitch), sp = sinf(pitch);
        float cy = cosf(yaw),   sy = sinf(yaw);
        // R = Rx @ Ry @ Rz (row-major)
        sRT[0] = cp * cy;                sRT[1] = -cp * sy;               sRT[2] = sp;
        sRT[3] = cr * sy + sr * sp * cy; sRT[4] = cr * cy - sr * sp * sy; sRT[5] = -sr * cp;
        sRT[6] = sr * sy - cr * sp * cy; sRT[7] = sr * cy + cr * sp * sy; sRT[8] = cr * cp;
        sRT[9] = *px; sRT[10] = *py; sRT[11] = *pz;
    }
    if (t < WARPS * SLOTS) mbar_init(mbar_base + 8u * t, 1);
    __syncthreads();   // only CTA-wide sync before the final reduction

    const float R00 = sRT[0], R01 = sRT[1], R02 = sRT[2];
    const float R10 = sRT[3], R11 = sRT[4], R12 = sRT[5];
    const float R20 = sRT[6], R21 = sRT[7], R22 = sRT[8];
    const float Tx  = sRT[9], Ty  = sRT[10], Tz = sRT[11];

    const int n_full = n_pts / TILE_PTS;         // 31250 full 128-pt tiles
    const int stride = NBLK * WARPS;             // 3552 warps chip-wide
    const int gw     = bid * WARPS + wid;
    const int count  = (n_full > gw) ? (n_full - gw + stride - 1) / stride : 0;

    const uint32_t ring  = smem_base + (uint32_t)(wid * SLOTS) * TILE_B;
    const uint32_t mring = mbar_base + (uint32_t)(wid * SLOTS) * 8u;
    float* const   ringf = (float*)(smem_raw + (size_t)(wid * SLOTS) * TILE_B);

    // ---- prologue: prefetch up to PREF tiles ----
    if (lane == 0) {
        const int pre = count < PREF ? count : PREF;
        for (int j = 0; j < pre; j++) {
            const size_t tile = (size_t)gw + (size_t)j * stride;
            mbar_expect_tx(mring + 8u * j, TILE_B);
            bulk_g2s(ring + (uint32_t)j * TILE_B, pts + tile * (TILE_PTS * 3),
                     TILE_B, mring + 8u * j);
        }
    }

    float obs_sum = 0.0f;

    // increment-wrap cursors (SLOTS=6 is not a power of 2)
    int slot = 0, phase = 0;        // consume cursor
    int nslot = PREF % SLOTS;       // prefetch-target cursor

    for (int j = 0; j < count; j++) {
        mbar_wait_parity(mring + 8u * slot, (uint32_t)phase);

        // ---- conflict-free compute: p = lane + 32*i, scalar 12B stride ----
        float* sp = ringf + (size_t)slot * (TILE_B / 4);

        #pragma unroll
        for (int i = 0; i < TILE_PTS / 32; i++) {
            const int e = 3 * (lane + 32 * i);
            const float d0 = sp[e + 0] - Tx;
            const float d1 = sp[e + 1] - Ty;
            const float d2 = sp[e + 2] - Tz;
            const float v0 = fmaf(d2, R20, fmaf(d1, R10, d0 * R00));
            const float v1 = fmaf(d2, R21, fmaf(d1, R11, d0 * R01));
            const float v2 = fmaf(d2, R22, fmaf(d1, R12, d0 * R02));

            const float ph0 = fmaf(600.0f, v0, 640.0f * v2);
            const float ph1 = fmaf(600.0f, v1, 360.0f * v2);
            // division-free: v2>1 (>0) makes these equivalent to u/w bounds
            const bool m = (v2 > 1.0f) & (v2 < 10.0f) &
                           (ph0 > v2) & (ph0 < 1279.0f * v2) &
                           (ph1 > v2) & (ph1 < 719.0f * v2);

            const float n2 = fmaf(v0, v0, fmaf(v1, v1, v2 * v2));
            const float dist = n2 * rsqrtf(n2);
            const float s = dist - 4.0f;
            // exp(-0.5*((d-4)/2)^2) = exp2(s*s * -(log2 e)/8)
            const float ob = exp2f(s * s * -0.18033688f);
            obs_sum += m ? ob : 0.0f;

            sp[e + 0] = m ? v0 : 0.0f;
            sp[e + 1] = m ? v1 : 0.0f;
            sp[e + 2] = m ? v2 : 0.0f;
        }

        // make STS visible to the async proxy, then elect-lane issues I/O
        asm volatile("fence.proxy.async.shared::cta;" ::: "memory");
        __syncwarp();

        if (lane == 0) {
            const size_t tile = (size_t)gw + (size_t)j * stride;
            bulk_s2g(out + tile * (TILE_PTS * 3), ring + (uint32_t)slot * TILE_B,
                     TILE_B);
            asm volatile("cp.async.bulk.commit_group;" ::: "memory");

            const int jn = j + PREF;
            if (jn < count) {
                // target slot was last stored as group j-2 (ring distance 6,
                // prefetch 4): allow only the 2 newest groups outstanding
                asm volatile("cp.async.bulk.wait_group.read 2;" ::: "memory");
                const size_t tile_n = (size_t)gw + (size_t)jn * stride;
                mbar_expect_tx(mring + 8u * nslot, TILE_B);
                bulk_g2s(ring + (uint32_t)nslot * TILE_B,
                         pts + tile_n * (TILE_PTS * 3), TILE_B,
                         mring + 8u * nslot);
            }
        }

        if (++slot == SLOTS) { slot = 0; phase ^= 1; }
        if (++nslot == SLOTS) { nslot = 0; }
    }

    if (lane == 0) {
        asm volatile("cp.async.bulk.wait_group.read 0;" ::: "memory");
    }

    // ---- tail points (n_pts % 128): scalar on block 0 / thread 0 ----
    if (bid == 0 && t == 0) {
        for (int idx = n_full * TILE_PTS; idx < n_pts; idx++) {
            const float d0 = pts[3 * idx + 0] - Tx;
            const float d1 = pts[3 * idx + 1] - Ty;
            const float d2 = pts[3 * idx + 2] - Tz;
            const float v0 = fmaf(d2, R20, fmaf(d1, R10, d0 * R00));
            const float v1 = fmaf(d2, R21, fmaf(d1, R11, d0 * R01));
            const float v2 = fmaf(d2, R22, fmaf(d1, R12, d0 * R02));
            const float ph0 = fmaf(600.0f, v0, 640.0f * v2);
            const float ph1 = fmaf(600.0f, v1, 360.0f * v2);
            const bool m = (v2 > 1.0f) & (v2 < 10.0f) &
                           (ph0 > v2) & (ph0 < 1279.0f * v2) &
                           (ph1 > v2) & (ph1 < 719.0f * v2);
            const float n2 = fmaf(v0, v0, fmaf(v1, v1, v2 * v2));
            const float dist = n2 * rsqrtf(n2);
            const float s = dist - 4.0f;
            obs_sum += m ? exp2f(s * s * -0.18033688f) : 0.0f;
            out[3 * idx + 0] = m ? v0 : 0.0f;
            out[3 * idx + 1] = m ? v1 : 0.0f;
            out[3 * idx + 2] = m ? v2 : 0.0f;
        }
    }

    // ---- reduction: warp -> block -> global atomic ----
    #pragma unroll
    for (int off = 16; off > 0; off >>= 1)
        obs_sum += __shfl_xor_sync(0xffffffffu, obs_sum, off);

    if (lane == 0) swarp[wid] = obs_sum;
    __syncthreads();

    if (wid == 0) {
        float s = (lane < WARPS) ? swarp[lane] : 0.0f;
        #pragma unroll
        for (int off = 16; off > 0; off >>= 1)
            s += __shfl_xor_sync(0xffffffffu, s, off);
        if (lane == 0) {
            atomicAdd(&g_sum, s);
            __threadfence();
            const unsigned int prev = atomicAdd(&g_count, 1u);
            if (prev == gridDim.x - 1u) {
                const float total = atomicAdd(&g_sum, 0.0f);
                out[loss_idx] = 1.0f / (total + 1e-6f);
                g_sum = 0.0f;       // reset for next graph replay
                g_count = 0u;
            }
        }
    }
}

extern "C" void kernel_launch(void* const* d_in, const int* in_sizes, int n_in,
                              void* d_out, int out_size) {
    const float* pts    = (const float*)d_in[0];
    const float* x      = (const float*)d_in[1];
    const float* y      = (const float*)d_in[2];
    const float* z      = (const float*)d_in[3];
    const float* roll   = (const float*)d_in[4];
    const float* pitch  = (const float*)d_in[5];
    const float* yaw    = (const float*)d_in[6];
    float* out = (float*)d_out;

    const int n_pts = in_sizes[0] / 3;       // 4,000,000
    const int loss_idx = out_size - 1;       // verts first, loss last

    cudaFuncSetAttribute(pose_warp_pipe_kernel,
                         cudaFuncAttributeMaxDynamicSharedMemorySize, SMEM_DYN);
    pose_warp_pipe_kernel<<<NBLK, THREADS, SMEM_DYN>>>(
        pts, x, y, z, roll, pitch, yaw, out, n_pts, loss_idx);
}

// round 9
// speedup vs baseline: 1.3321x; 1.3321x over previous
#include <cuda_runtime.h>
#include <cstdint>

// Model_55645596287458 — R8 = R6b with ONE change: pair-strided smem
// layout. Lane handles point-pairs p2 = lane + 32k (k<4); each pair is
// 3x float2 at float2-index 3*lane + 96k -> word banks 6*lane+{0..5},
// conflict-free per half-warp phase (6*dL % 32 != 0 for dL<16).
// Same wide-op count as R6b (12 LDS.64 + 12 STS.64 per 8 pts), zero
// conflicts, immediate addressing.
// Pipeline unchanged: 148 CTAs x 512 thr, 16 warps x 4-slot x 3KB rings,
// 3-deep TMA prefetch, per-warp bulk_group stores, no CTA barriers.

#define WARPS     16
#define THREADS   (WARPS * 32)
#define SLOTS     4
#define TILE_PTS  256
#define TILE_B    (TILE_PTS * 12)            // 3072
#define NBLK      148
#define PREF      3
#define SMEM_TILES (WARPS * SLOTS * TILE_B)  // 196608
#define SMEM_DYN   (SMEM_TILES + WARPS * SLOTS * 8)

__device__ float        g_sum   = 0.0f;
__device__ unsigned int g_count = 0u;

__device__ __forceinline__ void mbar_init(uint32_t a, uint32_t cnt) {
    asm volatile("mbarrier.init.shared.b64 [%0], %1;" :: "r"(a), "r"(cnt) : "memory");
}
__device__ __forceinline__ void mbar_expect_tx(uint32_t a, uint32_t bytes) {
    asm volatile("mbarrier.arrive.expect_tx.shared.b64 _, [%0], %1;"
                 :: "r"(a), "r"(bytes) : "memory");
}
__device__ __forceinline__ void mbar_wait_parity(uint32_t a, uint32_t parity) {
    asm volatile(
        "{\n\t.reg .pred P;\n\t"
        "LW_%=:\n\t"
        "mbarrier.try_wait.parity.acquire.cta.shared::cta.b64 P, [%0], %1, 0x989680;\n\t"
        "@P bra.uni LD_%=;\n\t"
        "bra.uni LW_%=;\n\t"
        "LD_%=:\n\t}"
        :: "r"(a), "r"(parity) : "memory");
}
__device__ __forceinline__ void bulk_g2s(uint32_t dst, const void* src,
                                         uint32_t bytes, uint32_t mbar) {
    asm volatile("cp.async.bulk.shared::cta.global.mbarrier::complete_tx::bytes "
                 "[%0], [%1], %2, [%3];"
                 :: "r"(dst), "l"(src), "r"(bytes), "r"(mbar) : "memory");
}
__device__ __forceinline__ void bulk_s2g(void* dst, uint32_t src, uint32_t bytes) {
    asm volatile("cp.async.bulk.global.shared::cta.bulk_group [%0], [%1], %2;"
                 :: "l"(dst), "r"(src), "r"(bytes) : "memory");
}

extern __shared__ char smem_raw[];

__global__ __launch_bounds__(THREADS, 1) void pose_warp_pipe_kernel(
    const float* __restrict__ pts,
    const float* __restrict__ px,  const float* __restrict__ py,
    const float* __restrict__ pz,  const float* __restrict__ proll,
    const float* __restrict__ ppitch, const float* __restrict__ pyaw,
    float* __restrict__ out, int n_pts, int loss_idx)
{
    __shared__ float sRT[12];
    __shared__ float swarp[WARPS];

    const int t    = threadIdx.x;
    const int lane = t & 31;
    const int wid  = t >> 5;
    const int bid  = blockIdx.x;

    const uint32_t smem_base = (uint32_t)__cvta_generic_to_shared(smem_raw);
    const uint32_t mbar_base = smem_base + SMEM_TILES;

    if (t == 0) {
        float roll = *proll, pitch = *ppitch, yaw = *pyaw;
        float cr = cosf(roll),  sr = sinf(roll);
        float cp = cosf(pitch), sp = sinf(pitch);
        float cy = cosf(yaw),   sy = sinf(yaw);
        // R = Rx @ Ry @ Rz (row-major)
        sRT[0] = cp * cy;                sRT[1] = -cp * sy;               sRT[2] = sp;
        sRT[3] = cr * sy + sr * sp * cy; sRT[4] = cr * cy - sr * sp * sy; sRT[5] = -sr * cp;
        sRT[6] = sr * sy - cr * sp * cy; sRT[7] = sr * cy + cr * sp * sy; sRT[8] = cr * cp;
        sRT[9] = *px; sRT[10] = *py; sRT[11] = *pz;
    }
    if (t < WARPS * SLOTS) mbar_init(mbar_base + 8u * t, 1);
    __syncthreads();   // only CTA-wide sync before the final reduction

    const float R00 = sRT[0], R01 = sRT[1], R02 = sRT[2];
    const float R10 = sRT[3], R11 = sRT[4], R12 = sRT[5];
    const float R20 = sRT[6], R21 = sRT[7], R22 = sRT[8];
    const float Tx  = sRT[9], Ty  = sRT[10], Tz = sRT[11];

    const int n_full = n_pts / TILE_PTS;         // 15625 full 256-pt tiles
    const int stride = NBLK * WARPS;             // 2368 warps chip-wide
    const int gw     = bid * WARPS + wid;
    const int count  = (n_full > gw) ? (n_full - gw + stride - 1) / stride : 0;

    const uint32_t ring  = smem_base + (uint32_t)(wid * SLOTS) * TILE_B;
    const uint32_t mring = mbar_base + (uint32_t)(wid * SLOTS) * 8u;

    // ---- prologue: prefetch up to PREF tiles ----
    if (lane == 0) {
        const int pre = count < PREF ? count : PREF;
        for (int j = 0; j < pre; j++) {
            const size_t tile = (size_t)gw + (size_t)j * stride;
            mbar_expect_tx(mring + 8u * j, TILE_B);
            bulk_g2s(ring + (uint32_t)j * TILE_B, pts + tile * (TILE_PTS * 3),
                     TILE_B, mring + 8u * j);
        }
    }

    float obs_sum = 0.0f;

    for (int j = 0; j < count; j++) {
        const int slot = j & (SLOTS - 1);
        mbar_wait_parity(mring + 8u * slot, (uint32_t)((j >> 2) & 1));

        // ---- conflict-free wide compute: pair p2 = lane + 32k ----
        // pair = 3 float2s at float2-index 3*lane + 96k (banks 6L+{0..5})
        float2* q0 = (float2*)(smem_raw + (size_t)(wid * SLOTS + slot) * TILE_B)
                     + 3 * lane;

        #pragma unroll
        for (int k = 0; k < 4; k++) {
            float2* q = q0 + 96 * k;
            const float2 A = q[0];
            const float2 B = q[1];
            const float2 C = q[2];
            const float p[6] = {A.x, A.y, B.x, B.y, C.x, C.y};
            float o[6];

            #pragma unroll
            for (int i = 0; i < 2; i++) {
                const float d0 = p[3 * i + 0] - Tx;
                const float d1 = p[3 * i + 1] - Ty;
                const float d2 = p[3 * i + 2] - Tz;
                const float v0 = fmaf(d2, R20, fmaf(d1, R10, d0 * R00));
                const float v1 = fmaf(d2, R21, fmaf(d1, R11, d0 * R01));
                const float v2 = fmaf(d2, R22, fmaf(d1, R12, d0 * R02));

                const float ph0 = fmaf(600.0f, v0, 640.0f * v2);
                const float ph1 = fmaf(600.0f, v1, 360.0f * v2);
                // division-free: v2>1 (>0) makes these equivalent to u/w bounds
                const bool m = (v2 > 1.0f) & (v2 < 10.0f) &
                               (ph0 > v2) & (ph0 < 1279.0f * v2) &
                               (ph1 > v2) & (ph1 < 719.0f * v2);

                const float n2 = fmaf(v0, v0, fmaf(v1, v1, v2 * v2));
                const float dist = n2 * rsqrtf(n2);
                const float s = dist - 4.0f;
                // exp(-0.5*((d-4)/2)^2) = exp2(s*s * -(log2 e)/8)
                const float e = exp2f(s * s * -0.18033688f);
                obs_sum += m ? e : 0.0f;

                o[3 * i + 0] = m ? v0 : 0.0f;
                o[3 * i + 1] = m ? v1 : 0.0f;
                o[3 * i + 2] = m ? v2 : 0.0f;
            }
            q[0] = make_float2(o[0], o[1]);
            q[1] = make_float2(o[2], o[3]);
            q[2] = make_float2(o[4], o[5]);
        }

        // make STS visible to the async proxy, then elect-lane issues I/O
        asm volatile("fence.proxy.async.shared::cta;" ::: "memory");
        __syncwarp();

        if (lane == 0) {
            const size_t tile = (size_t)gw + (size_t)j * stride;
            bulk_s2g(out + tile * (TILE_PTS * 3), ring + (uint32_t)slot * TILE_B,
                     TILE_B);
            asm volatile("cp.async.bulk.commit_group;" ::: "memory");

            const int jn = j + PREF;
            if (jn < count) {
                // slot (jn&3) = (j-1)&3 was stored as group j-1; allow only
                // the newest group (j) to still be reading smem before reload
                asm volatile("cp.async.bulk.wait_group.read 1;" ::: "memory");
                const int ns = jn & (SLOTS - 1);
                const size_t tile_n = (size_t)gw + (size_t)jn * stride;
                mbar_expect_tx(mring + 8u * ns, TILE_B);
                bulk_g2s(ring + (uint32_t)ns * TILE_B,
                         pts + tile_n * (TILE_PTS * 3), TILE_B, mring + 8u * ns);
            }
        }
    }

    if (lane == 0) {
        asm volatile("cp.async.bulk.wait_group.read 0;" ::: "memory");
    }

    // ---- tail points (n_pts % 256): scalar on block 0 / thread 0 ----
    if (bid == 0 && t == 0) {
        for (int idx = n_full * TILE_PTS; idx < n_pts; idx++) {
            const float d0 = pts[3 * idx + 0] - Tx;
            const float d1 = pts[3 * idx + 1] - Ty;
            const float d2 = pts[3 * idx + 2] - Tz;
            const float v0 = fmaf(d2, R20, fmaf(d1, R10, d0 * R00));
            const float v1 = fmaf(d2, R21, fmaf(d1, R11, d0 * R01));
            const float v2 = fmaf(d2, R22, fmaf(d1, R12, d0 * R02));
            const float ph0 = fmaf(600.0f, v0, 640.0f * v2);
            const float ph1 = fmaf(600.0f, v1, 360.0f * v2);
            const bool m = (v2 > 1.0f) & (v2 < 10.0f) &
                           (ph0 > v2) & (ph0 < 1279.0f * v2) &
                           (ph1 > v2) & (ph1 < 719.0f * v2);
            const float n2 = fmaf(v0, v0, fmaf(v1, v1, v2 * v2));
            const float dist = n2 * rsqrtf(n2);
            const float s = dist - 4.0f;
            obs_sum += m ? exp2f(s * s * -0.18033688f) : 0.0f;
            out[3 * idx + 0] = m ? v0 : 0.0f;
            out[3 * idx + 1] = m ? v1 : 0.0f;
            out[3 * idx + 2] = m ? v2 : 0.0f;
        }
    }

    // ---- reduction: warp -> block -> global atomic ----
    #pragma unroll
    for (int off = 16; off > 0; off >>= 1)
        obs_sum += __shfl_xor_sync(0xffffffffu, obs_sum, off);

    if (lane == 0) swarp[wid] = obs_sum;
    __syncthreads();

    if (wid == 0) {
        float s = (lane < WARPS) ? swarp[lane] : 0.0f;
        #pragma unroll
        for (int off = 8; off > 0; off >>= 1)
            s += __shfl_xor_sync(0xffffffffu, s, off);
        if (lane == 0) {
            atomicAdd(&g_sum, s);
            __threadfence();
            const unsigned int prev = atomicAdd(&g_count, 1u);
            if (prev == gridDim.x - 1u) {
                const float total = atomicAdd(&g_sum, 0.0f);
                out[loss_idx] = 1.0f / (total + 1e-6f);
                g_sum = 0.0f;       // reset for next graph replay
                g_count = 0u;
            }
        }
    }
}

extern "C" void kernel_launch(void* const* d_in, const int* in_sizes, int n_in,
                              void* d_out, int out_size) {
    const float* pts    = (const float*)d_in[0];
    const float* x      = (const float*)d_in[1];
    const float* y      = (const float*)d_in[2];
    const float* z      = (const float*)d_in[3];
    const float* roll   = (const float*)d_in[4];
    const float* pitch  = (const float*)d_in[5];
    const float* yaw    = (const float*)d_in[6];
    float* out = (float*)d_out;

    const int n_pts = in_sizes[0] / 3;       // 4,000,000
    const int loss_idx = out_size - 1;       // verts first, loss last

    cudaFuncSetAttribute(pose_warp_pipe_kernel,
                         cudaFuncAttributeMaxDynamicSharedMemorySize, SMEM_DYN);
    pose_warp_pipe_kernel<<<NBLK, THREADS, SMEM_DYN>>>(
        pts, x, y, z, roll, pitch, yaw, out, n_pts, loss_idx);
}